// round 12
// baseline (speedup 1.0000x reference)
#include <cuda_runtime.h>
#include <cuda_fp16.h>
#include <cstdint>

#define N_NODES 100000
#define N_EDGES 3200000
#define ET      (N_EDGES + N_NODES)   // 3,300,000 (edges + self loops)
#define CI      128
#define CO      64
#define NB_SCAN ((N_NODES + 1023) / 1024)   // 98

// ---------------- device scratch (static, no allocation) ----------------
__device__ __align__(16) __half g_xlh[(size_t)N_NODES * CO];  // 12.8 MB fp16 xl
__device__ float g_si[N_NODES];
__device__ float g_sj[N_NODES];
__device__ float g_rden[N_NODES];
__device__ float g_agg[(size_t)N_NODES * CO];   // normalized + bias
__device__ float g_bnsum[2 * CO];
__device__ int   g_deg[N_NODES];
__device__ int   g_off[N_NODES];
__device__ int   g_cursor[N_NODES];
__device__ int   g_bsum[NB_SCAN];
__device__ int   g_bpre[NB_SCAN];
__device__ int2  g_epack[ET];    // (src, float_bits(ex)) grouped by dst
__device__ float g_exorig[ET];   // ex in ORIGINAL edge order (coalesced)

// ---------------- packed f32x2 helpers ----------------
__device__ __forceinline__ unsigned long long pk2(float lo, float hi) {
    unsigned long long r;
    asm("mov.b64 %0, {%1, %2};" : "=l"(r) : "f"(lo), "f"(hi));
    return r;
}
__device__ __forceinline__ float2 upk2(unsigned long long v) {
    float2 f;
    asm("mov.b64 {%0, %1}, %2;" : "=f"(f.x), "=f"(f.y) : "l"(v));
    return f;
}
#define FMA2(d, a, b) asm("fma.rn.f32x2 %0, %1, %2, %0;" : "+l"(d) : "l"(a), "l"(b))

// ---------------- K0: init ----------------
__global__ __launch_bounds__(256) void k_init() {
    int i = blockIdx.x * 256 + threadIdx.x;
    if (i < N_NODES) g_deg[i] = 0;
    if (i < 2 * CO) g_bnsum[i] = 0.f;
}

// ---------------- K1: GEMM xl = x @ W^T + b, fused scores --------------
// 256 thr/block, 256 rows/block; thread = 4 rows x 16 cols; f32x2 FMA.
__global__ __launch_bounds__(256) void k_gemm(
    const float* __restrict__ x,  const float* __restrict__ w,
    const float* __restrict__ lb, const float* __restrict__ emb,
    const float* __restrict__ ai, const float* __restrict__ aj,
    const float* __restrict__ aei, const float* __restrict__ aej)
{
    __shared__ float wsT[128 * 68];   // [k][c], row padded to 68 floats
    int tid = threadIdx.x;
    for (int i = tid; i < CO * CI; i += 256) {
        int c = i >> 7, k = i & 127;  // w is [CO][CI] row-major
        wsT[k * 68 + c] = w[i];
    }
    __syncthreads();

    int rbase = blockIdx.x * 256;
    int rl = tid >> 2;                 // 0..63
    int g = (tid & 3) * 16;            // 16-col group
    int m[4]; bool v[4]; int mc[4];
#pragma unroll
    for (int r = 0; r < 4; r++) {
        m[r] = rbase + rl + r * 64;
        v[r] = (m[r] < N_NODES);
        mc[r] = v[r] ? m[r] : (N_NODES - 1);
    }
    const float* xr0 = x + (size_t)mc[0] * CI;
    const float* xr1 = x + (size_t)mc[1] * CI;
    const float* xr2 = x + (size_t)mc[2] * CI;
    const float* xr3 = x + (size_t)mc[3] * CI;

    unsigned long long acc[4][8];      // 4 rows x 8 f32x2 = 16 cols
#pragma unroll
    for (int r = 0; r < 4; r++)
#pragma unroll
        for (int t = 0; t < 8; t++) acc[r][t] = 0ull;

    for (int k0 = 0; k0 < 128; k0 += 4) {
        float4 xv0 = *(const float4*)(xr0 + k0);
        float4 xv1 = *(const float4*)(xr1 + k0);
        float4 xv2 = *(const float4*)(xr2 + k0);
        float4 xv3 = *(const float4*)(xr3 + k0);
#pragma unroll
        for (int q = 0; q < 4; q++) {
            unsigned long long xs0 = pk2((&xv0.x)[q], (&xv0.x)[q]);
            unsigned long long xs1 = pk2((&xv1.x)[q], (&xv1.x)[q]);
            unsigned long long xs2 = pk2((&xv2.x)[q], (&xv2.x)[q]);
            unsigned long long xs3 = pk2((&xv3.x)[q], (&xv3.x)[q]);
            const ulonglong2* wp = (const ulonglong2*)&wsT[(k0 + q) * 68 + g];
#pragma unroll
            for (int j = 0; j < 4; j++) {
                ulonglong2 wv = wp[j];               // LDS.128 = 2 packed pairs
                FMA2(acc[0][2*j],   xs0, wv.x); FMA2(acc[0][2*j+1], xs0, wv.y);
                FMA2(acc[1][2*j],   xs1, wv.x); FMA2(acc[1][2*j+1], xs1, wv.y);
                FMA2(acc[2][2*j],   xs2, wv.x); FMA2(acc[2][2*j+1], xs2, wv.y);
                FMA2(acc[3][2*j],   xs3, wv.x); FMA2(acc[3][2*j+1], xs3, wv.y);
            }
        }
    }

    // epilogue per row: bias, scores, fp16 xl store; reduce over 4 lanes
#pragma unroll
    for (int r = 0; r < 4; r++) {
        float p_i = 0.f, p_j = 0.f;
        unsigned hu[8];
#pragma unroll
        for (int t = 0; t < 8; t++) {
            float2 f = upk2(acc[r][t]);
            float o0 = f.x + __ldg(&lb[g + 2*t]);
            float o1 = f.y + __ldg(&lb[g + 2*t + 1]);
            p_i = fmaf(o0, __ldg(&ai[g + 2*t]),     p_i);
            p_i = fmaf(o1, __ldg(&ai[g + 2*t + 1]), p_i);
            p_j = fmaf(o0, __ldg(&aj[g + 2*t]),     p_j);
            p_j = fmaf(o1, __ldg(&aj[g + 2*t + 1]), p_j);
            __half2 hh = __floats2half2_rn(o0, o1);
            hu[t] = *reinterpret_cast<unsigned*>(&hh);
        }
        if (v[r]) {
            uint4* dstp = (uint4*)&g_xlh[(size_t)m[r] * CO + g];
            dstp[0] = make_uint4(hu[0], hu[1], hu[2], hu[3]);
            dstp[1] = make_uint4(hu[4], hu[5], hu[6], hu[7]);
        }
        const float* er = emb + (size_t)mc[r] * CO + g;
#pragma unroll
        for (int c = 0; c < 16; c += 4) {
            float4 ev = *(const float4*)(er + c);
#pragma unroll
            for (int q = 0; q < 4; q++) {
                p_i = fmaf((&ev.x)[q], __ldg(&aei[g + c + q]), p_i);
                p_j = fmaf((&ev.x)[q], __ldg(&aej[g + c + q]), p_j);
            }
        }
        p_i += __shfl_xor_sync(0xffffffffu, p_i, 1);
        p_j += __shfl_xor_sync(0xffffffffu, p_j, 1);
        p_i += __shfl_xor_sync(0xffffffffu, p_i, 2);
        p_j += __shfl_xor_sync(0xffffffffu, p_j, 2);
        if (v[r] && (tid & 3) == 0) { g_si[m[r]] = p_i; g_sj[m[r]] = p_j; }
    }
}

// ---------------- CSR build: histogram, scan, scatter -------------------
__global__ __launch_bounds__(256) void k_hist(const int* __restrict__ ei) {
    int e = blockIdx.x * 256 + threadIdx.x;
    if (e >= ET) return;
    int d = (e < N_EDGES) ? __ldg(&ei[N_EDGES + e]) : (e - N_EDGES);
    atomicAdd(&g_deg[d], 1);
}

__global__ __launch_bounds__(1024) void k_blocksum() {
    __shared__ int sh[1024];
    int i = blockIdx.x * 1024 + threadIdx.x;
    sh[threadIdx.x] = (i < N_NODES) ? g_deg[i] : 0;
    __syncthreads();
    for (int s = 512; s > 0; s >>= 1) {
        if (threadIdx.x < s) sh[threadIdx.x] += sh[threadIdx.x + s];
        __syncthreads();
    }
    if (threadIdx.x == 0) g_bsum[blockIdx.x] = sh[0];
}

// parallel exclusive scan of the 98 block sums (1 block, 128 threads)
__global__ __launch_bounds__(128) void k_scanbsum() {
    __shared__ int wtot[4];
    int t = threadIdx.x;
    int lane = t & 31, wid = t >> 5;
    int v = (t < NB_SCAN) ? g_bsum[t] : 0;
    int inc = v;
#pragma unroll
    for (int o = 1; o < 32; o <<= 1) {
        int n = __shfl_up_sync(0xffffffffu, inc, o);
        if (lane >= o) inc += n;
    }
    if (lane == 31) wtot[wid] = inc;
    __syncthreads();
    int ofs = 0;
    if (wid > 0) {
        for (int ww = 0; ww < 4; ww++) if (ww < wid) ofs += wtot[ww];
    }
    if (t < NB_SCAN) g_bpre[t] = ofs + inc - v;   // exclusive prefix
}

__global__ __launch_bounds__(1024) void k_scanfinal() {
    __shared__ int sh[2][1024];
    int i = blockIdx.x * 1024 + threadIdx.x;
    int t = threadIdx.x;
    int v = (i < N_NODES) ? g_deg[i] : 0;
    sh[0][t] = v;
    __syncthreads();
    int cur = 0;
#pragma unroll
    for (int ofs = 1; ofs < 1024; ofs <<= 1) {
        int nxt = cur ^ 1;
        int val = sh[cur][t];
        if (t >= ofs) val += sh[cur][t - ofs];
        sh[nxt][t] = val;
        __syncthreads();
        cur = nxt;
    }
    if (i < N_NODES) {
        int excl = sh[cur][t] - v + g_bpre[blockIdx.x];
        g_off[i] = excl;
        g_cursor[i] = excl;
    }
}

// scatter: compute ex once; random epack store + coalesced exorig store
__global__ __launch_bounds__(256) void k_scatter(const int* __restrict__ ei) {
    int e = blockIdx.x * 256 + threadIdx.x;
    if (e >= ET) return;
    int s, d;
    if (e < N_EDGES) { s = __ldg(&ei[e]); d = __ldg(&ei[N_EDGES + e]); }
    else             { s = e - N_EDGES; d = s; }
    float a = g_si[d] + g_sj[s];
    a = a > 0.f ? a : 0.2f * a;
    float ex = __expf(a);
    g_exorig[e] = ex;                        // coalesced
    int pos = atomicAdd(&g_cursor[d], 1);
    g_epack[pos] = make_int2(s, __float_as_int(ex));
}

// ---------------- K7: CSR aggregate + fused BN stats --------------------
// One warp per dst; grid EXACTLY 12500 blocks. Chunk metadata prefetched.
__global__ __launch_bounds__(256) void k_agg_csr(const float* __restrict__ bias) {
    __shared__ float bs1[64], bs2[64];
    int tid = threadIdx.x;
    if (tid < 64) { bs1[tid] = 0.f; bs2[tid] = 0.f; }
    __syncthreads();

    int d = (blockIdx.x * 256 + tid) >> 5;
    int lane = tid & 31;
    int start = __ldg(&g_off[d]);
    int end = (d == N_NODES - 1) ? ET : __ldg(&g_off[d + 1]);

    float acc0 = 0.f, acc1 = 0.f, denl = 0.f;
    int base = start;
    int nfull = (end - start) >> 5;           // number of full 32-chunks

    if (nfull > 0) {
        int2 se = g_epack[base + lane];       // prefetch chunk 0
        for (int ch = 0; ch < nfull; ch++) {
            int2 cur = se;
            if (ch + 1 < nfull) se = g_epack[base + 32 + lane];   // prefetch next
            float ex = __int_as_float(cur.y);
            denl += ex;
#pragma unroll 8
            for (int j = 0; j < 32; j++) {
                int sj   = __shfl_sync(0xffffffffu, cur.x, j);
                float xj = __shfl_sync(0xffffffffu, ex, j);
                __half2 h = *(const __half2*)&g_xlh[(size_t)sj * CO + lane * 2];
                float2 f = __half22float2(h);
                acc0 = fmaf(xj, f.x, acc0);
                acc1 = fmaf(xj, f.y, acc1);
            }
            base += 32;
        }
    }
    if (base < end) {
        int p = base + lane;
        int2 se = (p < end) ? g_epack[p] : make_int2(0, 0);
        float ex = __int_as_float(se.y);
        denl += ex;
        int cnt = end - base;
        for (int j = 0; j < cnt; j++) {
            int sj   = __shfl_sync(0xffffffffu, se.x, j);
            float xj = __shfl_sync(0xffffffffu, ex, j);
            __half2 h = *(const __half2*)&g_xlh[(size_t)sj * CO + lane * 2];
            float2 f = __half22float2(h);
            acc0 = fmaf(xj, f.x, acc0);
            acc1 = fmaf(xj, f.y, acc1);
        }
    }
#pragma unroll
    for (int o = 16; o; o >>= 1) denl += __shfl_xor_sync(0xffffffffu, denl, o);
    float rden = __frcp_rn(denl);
    if (lane == 0) g_rden[d] = rden;
    float r0 = acc0 * rden + __ldg(&bias[2 * lane]);
    float r1 = acc1 * rden + __ldg(&bias[2 * lane + 1]);
    *(float2*)&g_agg[(size_t)d * CO + lane * 2] = make_float2(r0, r1);

    atomicAdd(&bs1[2 * lane],     r0);
    atomicAdd(&bs1[2 * lane + 1], r1);
    atomicAdd(&bs2[2 * lane],     r0 * r0);
    atomicAdd(&bs2[2 * lane + 1], r1 * r1);

    __syncthreads();
    if (tid < 64) {
        atomicAdd(&g_bnsum[tid],      bs1[tid]);
        atomicAdd(&g_bnsum[64 + tid], bs2[tid]);
    }
}

// ---------------- K8: attention weights (coalesced) --------------------
__global__ __launch_bounds__(256) void k_att(const int* __restrict__ ei,
                                             float* __restrict__ att) {
    int e = blockIdx.x * 256 + threadIdx.x;
    if (e >= ET) return;
    int d = (e < N_EDGES) ? __ldg(&ei[N_EDGES + e]) : (e - N_EDGES);
    att[e] = g_exorig[e] * g_rden[d];
}

// ---------------- K9: BN apply + leaky-relu -> out ----------------------
__global__ __launch_bounds__(256) void k_out(const float* __restrict__ gamma,
                                             const float* __restrict__ beta,
                                             float* __restrict__ out) {
    int i = blockIdx.x * 256 + threadIdx.x;
    if (i >= N_NODES * CO) return;
    int c = i & 63;
    float inv_n = 1.f / (float)N_NODES;
    float mu  = g_bnsum[c] * inv_n;
    float var = g_bnsum[64 + c] * inv_n - mu * mu;
    float v = g_agg[i];   // already includes bias
    float o = __ldg(&gamma[c]) * (v - mu) * rsqrtf(var + 1e-5f) + __ldg(&beta[c]);
    out[i] = o > 0.f ? o : 0.01f * o;
}

// ---------------- launch (single stream) ----------------
extern "C" void kernel_launch(void* const* d_in, const int* in_sizes, int n_in,
                              void* d_out, int out_size) {
    const float* x     = (const float*)d_in[0];
    const int*   ei    = (const int*)  d_in[1];
    const float* emb   = (const float*)d_in[2];
    const float* lw    = (const float*)d_in[3];
    const float* lb    = (const float*)d_in[4];
    const float* ai    = (const float*)d_in[5];
    const float* aj    = (const float*)d_in[6];
    const float* aei   = (const float*)d_in[7];
    const float* aej   = (const float*)d_in[8];
    const float* bias  = (const float*)d_in[9];
    const float* gamma = (const float*)d_in[10];
    const float* beta  = (const float*)d_in[11];

    float* out = (float*)d_out;                  // [N, 64]
    float* att = out + (size_t)N_NODES * CO;     // [ET, 1, 1]

    k_init     <<<(N_NODES + 255) / 256, 256>>>();
    k_gemm     <<<(N_NODES + 255) / 256, 256>>>(x, lw, lb, emb, ai, aj, aei, aej);
    k_hist     <<<(ET + 255) / 256, 256>>>(ei);
    k_blocksum <<<NB_SCAN, 1024>>>();
    k_scanbsum <<<1, 128>>>();
    k_scanfinal<<<NB_SCAN, 1024>>>();
    k_scatter  <<<(ET + 255) / 256, 256>>>(ei);
    k_agg_csr  <<<(N_NODES * 32) / 256, 256>>>(bias);
    k_att      <<<(ET + 255) / 256, 256>>>(ei, att);
    k_out      <<<(N_NODES * CO + 255) / 256, 256>>>(gamma, beta, out);
}

// round 13
// speedup vs baseline: 1.0787x; 1.0787x over previous
#include <cuda_runtime.h>
#include <cuda_fp16.h>
#include <cstdint>

#define N_NODES 100000
#define N_EDGES 3200000
#define ET      (N_EDGES + N_NODES)   // 3,300,000 (edges + self loops)
#define CI      128
#define CO      64
#define NB_SCAN ((N_NODES + 1023) / 1024)   // 98

// ---------------- device scratch (static, no allocation) ----------------
__device__ __align__(16) __half g_xlh[(size_t)N_NODES * CO];  // 12.8 MB fp16 xl
__device__ float g_si[N_NODES];
__device__ float g_sj[N_NODES];
__device__ float g_rden[N_NODES];
__device__ float g_agg[(size_t)N_NODES * CO];   // normalized + bias
__device__ float g_bnsum[2 * CO];
__device__ int   g_deg[N_NODES];
__device__ int   g_off[N_NODES];
__device__ int   g_cursor[N_NODES];
__device__ int   g_bsum[NB_SCAN];
__device__ int   g_bpre[NB_SCAN];
__device__ int2  g_epack[ET];    // (src, float_bits(ex)) grouped by dst
__device__ float g_exorig[ET];   // ex in ORIGINAL edge order (coalesced)

// ---------------- packed f32x2 helpers ----------------
__device__ __forceinline__ unsigned long long pk2(float lo, float hi) {
    unsigned long long r;
    asm("mov.b64 %0, {%1, %2};" : "=l"(r) : "f"(lo), "f"(hi));
    return r;
}
__device__ __forceinline__ float2 upk2(unsigned long long v) {
    float2 f;
    asm("mov.b64 {%0, %1}, %2;" : "=f"(f.x), "=f"(f.y) : "l"(v));
    return f;
}
#define FMA2(d, a, b) asm("fma.rn.f32x2 %0, %1, %2, %0;" : "+l"(d) : "l"(a), "l"(b))

// ---------------- K0: init ----------------
__global__ __launch_bounds__(256) void k_init() {
    int i = blockIdx.x * 256 + threadIdx.x;
    if (i < N_NODES) g_deg[i] = 0;
    if (i < 2 * CO) g_bnsum[i] = 0.f;
}

// ---------------- K1: GEMM xl = x @ W^T + b, fused scores --------------
// 256 thr/block, 256 rows/block; thread = 4 rows x 16 cols; f32x2 FMA.
__global__ __launch_bounds__(256) void k_gemm(
    const float* __restrict__ x,  const float* __restrict__ w,
    const float* __restrict__ lb, const float* __restrict__ emb,
    const float* __restrict__ ai, const float* __restrict__ aj,
    const float* __restrict__ aei, const float* __restrict__ aej)
{
    __shared__ float wsT[128 * 68];   // [k][c], row padded to 68 floats
    int tid = threadIdx.x;
    for (int i = tid; i < CO * CI; i += 256) {
        int c = i >> 7, k = i & 127;  // w is [CO][CI] row-major
        wsT[k * 68 + c] = w[i];
    }
    __syncthreads();

    int rbase = blockIdx.x * 256;
    int rl = tid >> 2;                 // 0..63
    int g = (tid & 3) * 16;            // 16-col group
    int m[4]; bool v[4]; int mc[4];
#pragma unroll
    for (int r = 0; r < 4; r++) {
        m[r] = rbase + rl + r * 64;
        v[r] = (m[r] < N_NODES);
        mc[r] = v[r] ? m[r] : (N_NODES - 1);
    }
    const float* xr0 = x + (size_t)mc[0] * CI;
    const float* xr1 = x + (size_t)mc[1] * CI;
    const float* xr2 = x + (size_t)mc[2] * CI;
    const float* xr3 = x + (size_t)mc[3] * CI;

    unsigned long long acc[4][8];      // 4 rows x 8 f32x2 = 16 cols
#pragma unroll
    for (int r = 0; r < 4; r++)
#pragma unroll
        for (int t = 0; t < 8; t++) acc[r][t] = 0ull;

    for (int k0 = 0; k0 < 128; k0 += 4) {
        float4 xv0 = *(const float4*)(xr0 + k0);
        float4 xv1 = *(const float4*)(xr1 + k0);
        float4 xv2 = *(const float4*)(xr2 + k0);
        float4 xv3 = *(const float4*)(xr3 + k0);
#pragma unroll
        for (int q = 0; q < 4; q++) {
            unsigned long long xs0 = pk2((&xv0.x)[q], (&xv0.x)[q]);
            unsigned long long xs1 = pk2((&xv1.x)[q], (&xv1.x)[q]);
            unsigned long long xs2 = pk2((&xv2.x)[q], (&xv2.x)[q]);
            unsigned long long xs3 = pk2((&xv3.x)[q], (&xv3.x)[q]);
            const ulonglong2* wp = (const ulonglong2*)&wsT[(k0 + q) * 68 + g];
#pragma unroll
            for (int j = 0; j < 4; j++) {
                ulonglong2 wv = wp[j];               // LDS.128 = 2 packed pairs
                FMA2(acc[0][2*j],   xs0, wv.x); FMA2(acc[0][2*j+1], xs0, wv.y);
                FMA2(acc[1][2*j],   xs1, wv.x); FMA2(acc[1][2*j+1], xs1, wv.y);
                FMA2(acc[2][2*j],   xs2, wv.x); FMA2(acc[2][2*j+1], xs2, wv.y);
                FMA2(acc[3][2*j],   xs3, wv.x); FMA2(acc[3][2*j+1], xs3, wv.y);
            }
        }
    }

    // epilogue per row: bias, scores, fp16 xl store; reduce over 4 lanes
#pragma unroll
    for (int r = 0; r < 4; r++) {
        float p_i = 0.f, p_j = 0.f;
        unsigned hu[8];
#pragma unroll
        for (int t = 0; t < 8; t++) {
            float2 f = upk2(acc[r][t]);
            float o0 = f.x + __ldg(&lb[g + 2*t]);
            float o1 = f.y + __ldg(&lb[g + 2*t + 1]);
            p_i = fmaf(o0, __ldg(&ai[g + 2*t]),     p_i);
            p_i = fmaf(o1, __ldg(&ai[g + 2*t + 1]), p_i);
            p_j = fmaf(o0, __ldg(&aj[g + 2*t]),     p_j);
            p_j = fmaf(o1, __ldg(&aj[g + 2*t + 1]), p_j);
            __half2 hh = __floats2half2_rn(o0, o1);
            hu[t] = *reinterpret_cast<unsigned*>(&hh);
        }
        if (v[r]) {
            uint4* dstp = (uint4*)&g_xlh[(size_t)m[r] * CO + g];
            dstp[0] = make_uint4(hu[0], hu[1], hu[2], hu[3]);
            dstp[1] = make_uint4(hu[4], hu[5], hu[6], hu[7]);
        }
        const float* er = emb + (size_t)mc[r] * CO + g;
#pragma unroll
        for (int c = 0; c < 16; c += 4) {
            float4 ev = *(const float4*)(er + c);
#pragma unroll
            for (int q = 0; q < 4; q++) {
                p_i = fmaf((&ev.x)[q], __ldg(&aei[g + c + q]), p_i);
                p_j = fmaf((&ev.x)[q], __ldg(&aej[g + c + q]), p_j);
            }
        }
        p_i += __shfl_xor_sync(0xffffffffu, p_i, 1);
        p_j += __shfl_xor_sync(0xffffffffu, p_j, 1);
        p_i += __shfl_xor_sync(0xffffffffu, p_i, 2);
        p_j += __shfl_xor_sync(0xffffffffu, p_j, 2);
        if (v[r] && (tid & 3) == 0) { g_si[m[r]] = p_i; g_sj[m[r]] = p_j; }
    }
}

// ---------------- CSR build: histogram, scan, scatter -------------------
__global__ __launch_bounds__(256) void k_hist(const int* __restrict__ ei) {
    int e = blockIdx.x * 256 + threadIdx.x;
    if (e >= ET) return;
    int d = (e < N_EDGES) ? __ldg(&ei[N_EDGES + e]) : (e - N_EDGES);
    atomicAdd(&g_deg[d], 1);
}

__global__ __launch_bounds__(1024) void k_blocksum() {
    __shared__ int sh[1024];
    int i = blockIdx.x * 1024 + threadIdx.x;
    sh[threadIdx.x] = (i < N_NODES) ? g_deg[i] : 0;
    __syncthreads();
    for (int s = 512; s > 0; s >>= 1) {
        if (threadIdx.x < s) sh[threadIdx.x] += sh[threadIdx.x + s];
        __syncthreads();
    }
    if (threadIdx.x == 0) g_bsum[blockIdx.x] = sh[0];
}

// parallel exclusive scan of the 98 block sums (1 block, 128 threads)
__global__ __launch_bounds__(128) void k_scanbsum() {
    __shared__ int wtot[4];
    int t = threadIdx.x;
    int lane = t & 31, wid = t >> 5;
    int v = (t < NB_SCAN) ? g_bsum[t] : 0;
    int inc = v;
#pragma unroll
    for (int o = 1; o < 32; o <<= 1) {
        int n = __shfl_up_sync(0xffffffffu, inc, o);
        if (lane >= o) inc += n;
    }
    if (lane == 31) wtot[wid] = inc;
    __syncthreads();
    int ofs = 0;
    if (wid > 0) {
        for (int ww = 0; ww < 4; ww++) if (ww < wid) ofs += wtot[ww];
    }
    if (t < NB_SCAN) g_bpre[t] = ofs + inc - v;   // exclusive prefix
}

__global__ __launch_bounds__(1024) void k_scanfinal() {
    __shared__ int sh[2][1024];
    int i = blockIdx.x * 1024 + threadIdx.x;
    int t = threadIdx.x;
    int v = (i < N_NODES) ? g_deg[i] : 0;
    sh[0][t] = v;
    __syncthreads();
    int cur = 0;
#pragma unroll
    for (int ofs = 1; ofs < 1024; ofs <<= 1) {
        int nxt = cur ^ 1;
        int val = sh[cur][t];
        if (t >= ofs) val += sh[cur][t - ofs];
        sh[nxt][t] = val;
        __syncthreads();
        cur = nxt;
    }
    if (i < N_NODES) {
        int excl = sh[cur][t] - v + g_bpre[blockIdx.x];
        g_off[i] = excl;
        g_cursor[i] = excl;
    }
}

// scatter: compute ex once; random epack store + coalesced exorig store
__global__ __launch_bounds__(256) void k_scatter(const int* __restrict__ ei) {
    int e = blockIdx.x * 256 + threadIdx.x;
    if (e >= ET) return;
    int s, d;
    if (e < N_EDGES) { s = __ldg(&ei[e]); d = __ldg(&ei[N_EDGES + e]); }
    else             { s = e - N_EDGES; d = s; }
    float a = g_si[d] + g_sj[s];
    a = a > 0.f ? a : 0.2f * a;
    float ex = __expf(a);
    g_exorig[e] = ex;                        // coalesced
    int pos = atomicAdd(&g_cursor[d], 1);
    g_epack[pos] = make_int2(s, __float_as_int(ex));
}

// ---------------- K7: CSR aggregate + fused BN stats --------------------
// One warp per dst node; grid is EXACTLY 12500 blocks (100000 warps).
// NO metadata prefetch (measured +12-18us regression with it).
__global__ __launch_bounds__(256) void k_agg_csr(const float* __restrict__ bias) {
    __shared__ float bs1[64], bs2[64];
    int tid = threadIdx.x;
    if (tid < 64) { bs1[tid] = 0.f; bs2[tid] = 0.f; }
    __syncthreads();

    int d = (blockIdx.x * 256 + tid) >> 5;
    int lane = tid & 31;
    int start = __ldg(&g_off[d]);
    int end = (d == N_NODES - 1) ? ET : __ldg(&g_off[d + 1]);

    float acc0 = 0.f, acc1 = 0.f, denl = 0.f;
    int base = start;
    for (; base + 32 <= end; base += 32) {          // full-chunk fast path
        int2 se = g_epack[base + lane];
        float ex = __int_as_float(se.y);
        denl += ex;
#pragma unroll 8
        for (int j = 0; j < 32; j++) {
            int sj   = __shfl_sync(0xffffffffu, se.x, j);
            float xj = __shfl_sync(0xffffffffu, ex, j);
            __half2 h = *(const __half2*)&g_xlh[(size_t)sj * CO + lane * 2];
            float2 f = __half22float2(h);
            acc0 = fmaf(xj, f.x, acc0);
            acc1 = fmaf(xj, f.y, acc1);
        }
    }
    if (base < end) {
        int p = base + lane;
        int2 se = (p < end) ? g_epack[p] : make_int2(0, 0);
        float ex = __int_as_float(se.y);   // 0 bits -> 0.0f
        denl += ex;
        int cnt = end - base;
        for (int j = 0; j < cnt; j++) {
            int sj   = __shfl_sync(0xffffffffu, se.x, j);
            float xj = __shfl_sync(0xffffffffu, ex, j);
            __half2 h = *(const __half2*)&g_xlh[(size_t)sj * CO + lane * 2];
            float2 f = __half22float2(h);
            acc0 = fmaf(xj, f.x, acc0);
            acc1 = fmaf(xj, f.y, acc1);
        }
    }
#pragma unroll
    for (int o = 16; o; o >>= 1) denl += __shfl_xor_sync(0xffffffffu, denl, o);
    float rden = __frcp_rn(denl);
    if (lane == 0) g_rden[d] = rden;
    float r0 = acc0 * rden + __ldg(&bias[2 * lane]);
    float r1 = acc1 * rden + __ldg(&bias[2 * lane + 1]);
    *(float2*)&g_agg[(size_t)d * CO + lane * 2] = make_float2(r0, r1);

    atomicAdd(&bs1[2 * lane],     r0);
    atomicAdd(&bs1[2 * lane + 1], r1);
    atomicAdd(&bs2[2 * lane],     r0 * r0);
    atomicAdd(&bs2[2 * lane + 1], r1 * r1);

    __syncthreads();
    if (tid < 64) {
        atomicAdd(&g_bnsum[tid],      bs1[tid]);
        atomicAdd(&g_bnsum[64 + tid], bs2[tid]);
    }
}

// ---------------- K8: attention weights (coalesced) --------------------
__global__ __launch_bounds__(256) void k_att(const int* __restrict__ ei,
                                             float* __restrict__ att) {
    int e = blockIdx.x * 256 + threadIdx.x;
    if (e >= ET) return;
    int d = (e < N_EDGES) ? __ldg(&ei[N_EDGES + e]) : (e - N_EDGES);
    att[e] = g_exorig[e] * g_rden[d];
}

// ---------------- K9: BN apply + leaky-relu -> out ----------------------
__global__ __launch_bounds__(256) void k_out(const float* __restrict__ gamma,
                                             const float* __restrict__ beta,
                                             float* __restrict__ out) {
    int i = blockIdx.x * 256 + threadIdx.x;
    if (i >= N_NODES * CO) return;
    int c = i & 63;
    float inv_n = 1.f / (float)N_NODES;
    float mu  = g_bnsum[c] * inv_n;
    float var = g_bnsum[64 + c] * inv_n - mu * mu;
    float v = g_agg[i];   // already includes bias
    float o = __ldg(&gamma[c]) * (v - mu) * rsqrtf(var + 1e-5f) + __ldg(&beta[c]);
    out[i] = o > 0.f ? o : 0.01f * o;
}

// ---------------- launch (single stream) ----------------
extern "C" void kernel_launch(void* const* d_in, const int* in_sizes, int n_in,
                              void* d_out, int out_size) {
    const float* x     = (const float*)d_in[0];
    const int*   ei    = (const int*)  d_in[1];
    const float* emb   = (const float*)d_in[2];
    const float* lw    = (const float*)d_in[3];
    const float* lb    = (const float*)d_in[4];
    const float* ai    = (const float*)d_in[5];
    const float* aj    = (const float*)d_in[6];
    const float* aei   = (const float*)d_in[7];
    const float* aej   = (const float*)d_in[8];
    const float* bias  = (const float*)d_in[9];
    const float* gamma = (const float*)d_in[10];
    const float* beta  = (const float*)d_in[11];

    float* out = (float*)d_out;                  // [N, 64]
    float* att = out + (size_t)N_NODES * CO;     // [ET, 1, 1]

    k_init     <<<(N_NODES + 255) / 256, 256>>>();
    k_gemm     <<<(N_NODES + 255) / 256, 256>>>(x, lw, lb, emb, ai, aj, aei, aej);
    k_hist     <<<(ET + 255) / 256, 256>>>(ei);
    k_blocksum <<<NB_SCAN, 1024>>>();
    k_scanbsum <<<1, 128>>>();
    k_scanfinal<<<NB_SCAN, 1024>>>();
    k_scatter  <<<(ET + 255) / 256, 256>>>(ei);
    k_agg_csr  <<<(N_NODES * 32) / 256, 256>>>(bias);
    k_att      <<<(ET + 255) / 256, 256>>>(ei, att);
    k_out      <<<(N_NODES * CO + 255) / 256, 256>>>(gamma, beta, out);
}

// round 14
// speedup vs baseline: 1.0792x; 1.0005x over previous
#include <cuda_runtime.h>
#include <cuda_fp16.h>
#include <cstdint>

#define N_NODES 100000
#define N_EDGES 3200000
#define ET      (N_EDGES + N_NODES)   // 3,300,000 (edges + self loops)
#define CI      128
#define CO      64
#define NB_SCAN ((N_NODES + 1023) / 1024)   // 98

// ---------------- device scratch (static, no allocation) ----------------
__device__ __align__(16) __half g_xlh[(size_t)N_NODES * CO];  // 12.8 MB fp16 xl
__device__ float g_si[N_NODES];
__device__ float g_sj[N_NODES];
__device__ float g_rden[N_NODES];
__device__ float g_agg[(size_t)N_NODES * CO];   // normalized + bias
__device__ float g_bnsum[2 * CO];
__device__ int   g_deg[N_NODES];
__device__ int   g_off[N_NODES];
__device__ int   g_cursor[N_NODES];
__device__ int   g_bsum[NB_SCAN];
__device__ int   g_bflag[NB_SCAN];
__device__ int2  g_epack[ET];    // (src, float_bits(ex)) grouped by dst
__device__ float g_exorig[ET];   // ex in ORIGINAL edge order (coalesced)

// ---------------- packed f32x2 helpers ----------------
__device__ __forceinline__ unsigned long long pk2(float lo, float hi) {
    unsigned long long r;
    asm("mov.b64 %0, {%1, %2};" : "=l"(r) : "f"(lo), "f"(hi));
    return r;
}
__device__ __forceinline__ float2 upk2(unsigned long long v) {
    float2 f;
    asm("mov.b64 {%0, %1}, %2;" : "=f"(f.x), "=f"(f.y) : "l"(v));
    return f;
}
#define FMA2(d, a, b) asm("fma.rn.f32x2 %0, %1, %2, %0;" : "+l"(d) : "l"(a), "l"(b))

// ---------------- K0: init ----------------
__global__ __launch_bounds__(256) void k_init() {
    int i = blockIdx.x * 256 + threadIdx.x;
    if (i < N_NODES) g_deg[i] = 0;
    if (i < 2 * CO) g_bnsum[i] = 0.f;
    if (i < NB_SCAN) g_bflag[i] = 0;
}

// ---------------- K1: GEMM xl = x @ W^T + b, fused scores --------------
// 256 thr/block, 256 rows/block; thread = 4 rows x 16 cols; f32x2 FMA.
__global__ __launch_bounds__(256) void k_gemm(
    const float* __restrict__ x,  const float* __restrict__ w,
    const float* __restrict__ lb, const float* __restrict__ emb,
    const float* __restrict__ ai, const float* __restrict__ aj,
    const float* __restrict__ aei, const float* __restrict__ aej)
{
    __shared__ float wsT[128 * 68];   // [k][c], row padded to 68 floats
    int tid = threadIdx.x;
    for (int i = tid; i < CO * CI; i += 256) {
        int c = i >> 7, k = i & 127;  // w is [CO][CI] row-major
        wsT[k * 68 + c] = w[i];
    }
    __syncthreads();

    int rbase = blockIdx.x * 256;
    int rl = tid >> 2;                 // 0..63
    int g = (tid & 3) * 16;            // 16-col group
    int m[4]; bool v[4]; int mc[4];
#pragma unroll
    for (int r = 0; r < 4; r++) {
        m[r] = rbase + rl + r * 64;
        v[r] = (m[r] < N_NODES);
        mc[r] = v[r] ? m[r] : (N_NODES - 1);
    }
    const float* xr0 = x + (size_t)mc[0] * CI;
    const float* xr1 = x + (size_t)mc[1] * CI;
    const float* xr2 = x + (size_t)mc[2] * CI;
    const float* xr3 = x + (size_t)mc[3] * CI;

    unsigned long long acc[4][8];      // 4 rows x 8 f32x2 = 16 cols
#pragma unroll
    for (int r = 0; r < 4; r++)
#pragma unroll
        for (int t = 0; t < 8; t++) acc[r][t] = 0ull;

    for (int k0 = 0; k0 < 128; k0 += 4) {
        float4 xv0 = *(const float4*)(xr0 + k0);
        float4 xv1 = *(const float4*)(xr1 + k0);
        float4 xv2 = *(const float4*)(xr2 + k0);
        float4 xv3 = *(const float4*)(xr3 + k0);
#pragma unroll
        for (int q = 0; q < 4; q++) {
            unsigned long long xs0 = pk2((&xv0.x)[q], (&xv0.x)[q]);
            unsigned long long xs1 = pk2((&xv1.x)[q], (&xv1.x)[q]);
            unsigned long long xs2 = pk2((&xv2.x)[q], (&xv2.x)[q]);
            unsigned long long xs3 = pk2((&xv3.x)[q], (&xv3.x)[q]);
            const ulonglong2* wp = (const ulonglong2*)&wsT[(k0 + q) * 68 + g];
#pragma unroll
            for (int j = 0; j < 4; j++) {
                ulonglong2 wv = wp[j];               // LDS.128 = 2 packed pairs
                FMA2(acc[0][2*j],   xs0, wv.x); FMA2(acc[0][2*j+1], xs0, wv.y);
                FMA2(acc[1][2*j],   xs1, wv.x); FMA2(acc[1][2*j+1], xs1, wv.y);
                FMA2(acc[2][2*j],   xs2, wv.x); FMA2(acc[2][2*j+1], xs2, wv.y);
                FMA2(acc[3][2*j],   xs3, wv.x); FMA2(acc[3][2*j+1], xs3, wv.y);
            }
        }
    }

    // epilogue per row: bias, scores, fp16 xl store; reduce over 4 lanes
#pragma unroll
    for (int r = 0; r < 4; r++) {
        float p_i = 0.f, p_j = 0.f;
        unsigned hu[8];
#pragma unroll
        for (int t = 0; t < 8; t++) {
            float2 f = upk2(acc[r][t]);
            float o0 = f.x + __ldg(&lb[g + 2*t]);
            float o1 = f.y + __ldg(&lb[g + 2*t + 1]);
            p_i = fmaf(o0, __ldg(&ai[g + 2*t]),     p_i);
            p_i = fmaf(o1, __ldg(&ai[g + 2*t + 1]), p_i);
            p_j = fmaf(o0, __ldg(&aj[g + 2*t]),     p_j);
            p_j = fmaf(o1, __ldg(&aj[g + 2*t + 1]), p_j);
            __half2 hh = __floats2half2_rn(o0, o1);
            hu[t] = *reinterpret_cast<unsigned*>(&hh);
        }
        if (v[r]) {
            uint4* dstp = (uint4*)&g_xlh[(size_t)m[r] * CO + g];
            dstp[0] = make_uint4(hu[0], hu[1], hu[2], hu[3]);
            dstp[1] = make_uint4(hu[4], hu[5], hu[6], hu[7]);
        }
        const float* er = emb + (size_t)mc[r] * CO + g;
#pragma unroll
        for (int c = 0; c < 16; c += 4) {
            float4 ev = *(const float4*)(er + c);
#pragma unroll
            for (int q = 0; q < 4; q++) {
                p_i = fmaf((&ev.x)[q], __ldg(&aei[g + c + q]), p_i);
                p_j = fmaf((&ev.x)[q], __ldg(&aej[g + c + q]), p_j);
            }
        }
        p_i += __shfl_xor_sync(0xffffffffu, p_i, 1);
        p_j += __shfl_xor_sync(0xffffffffu, p_j, 1);
        p_i += __shfl_xor_sync(0xffffffffu, p_i, 2);
        p_j += __shfl_xor_sync(0xffffffffu, p_j, 2);
        if (v[r] && (tid & 3) == 0) { g_si[m[r]] = p_i; g_sj[m[r]] = p_j; }
    }
}

// ---------------- CSR build: histogram + single-pass scan ---------------
__global__ __launch_bounds__(256) void k_hist(const int* __restrict__ ei) {
    int e = blockIdx.x * 256 + threadIdx.x;
    if (e >= ET) return;
    int d = (e < N_EDGES) ? __ldg(&ei[N_EDGES + e]) : (e - N_EDGES);
    atomicAdd(&g_deg[d], 1);
}

// One-pass chained scan: 98 blocks (< 148 SMs -> all resident wave 1).
// Each block scans its 1024 degs, publishes total (fence + flag), then
// 32 lanes poll lower-indexed blocks' flags to build the exclusive prefix.
// A block publishes BEFORE waiting -> no circular dependency.
__global__ __launch_bounds__(1024) void k_scan() {
    __shared__ int sh[2][1024];
    __shared__ int bpre_sh;
    int b = blockIdx.x;
    int t = threadIdx.x;
    int i = b * 1024 + t;
    int v = (i < N_NODES) ? g_deg[i] : 0;
    sh[0][t] = v;
    __syncthreads();
    int cur = 0;
#pragma unroll
    for (int ofs = 1; ofs < 1024; ofs <<= 1) {
        int nxt = cur ^ 1;
        int val = sh[cur][t];
        if (t >= ofs) val += sh[cur][t - ofs];
        sh[nxt][t] = val;
        __syncthreads();
        cur = nxt;
    }
    // publish this block's total
    if (t == 0) {
        g_bsum[b] = sh[cur][1023];
        __threadfence();
        atomicExch(&g_bflag[b], 1);
    }
    // exclusive block prefix via poll (warp 0)
    if (t < 32) {
        int acc = 0;
        for (int p = t; p < b; p += 32) {
            while (atomicAdd(&g_bflag[p], 0) == 0) { }
            acc += atomicAdd(&g_bsum[p], 0);
        }
#pragma unroll
        for (int o = 16; o; o >>= 1) acc += __shfl_xor_sync(0xffffffffu, acc, o);
        if (t == 0) bpre_sh = acc;
    }
    __syncthreads();
    if (i < N_NODES) {
        int excl = sh[cur][t] - v + bpre_sh;
        g_off[i] = excl;
        g_cursor[i] = excl;
    }
}

// scatter: compute ex once; random epack store + coalesced exorig store
__global__ __launch_bounds__(256) void k_scatter(const int* __restrict__ ei) {
    int e = blockIdx.x * 256 + threadIdx.x;
    if (e >= ET) return;
    int s, d;
    if (e < N_EDGES) { s = __ldg(&ei[e]); d = __ldg(&ei[N_EDGES + e]); }
    else             { s = e - N_EDGES; d = s; }
    float a = g_si[d] + g_sj[s];
    a = a > 0.f ? a : 0.2f * a;
    float ex = __expf(a);
    g_exorig[e] = ex;                        // coalesced
    int pos = atomicAdd(&g_cursor[d], 1);
    g_epack[pos] = make_int2(s, __float_as_int(ex));
}

// ---------------- K7: CSR aggregate + fused BN stats --------------------
// One warp per dst node; grid is EXACTLY 12500 blocks (100000 warps).
// NO metadata prefetch (measured +12-18us regression with it).
__global__ __launch_bounds__(256) void k_agg_csr(const float* __restrict__ bias) {
    __shared__ float bs1[64], bs2[64];
    int tid = threadIdx.x;
    if (tid < 64) { bs1[tid] = 0.f; bs2[tid] = 0.f; }
    __syncthreads();

    int d = (blockIdx.x * 256 + tid) >> 5;
    int lane = tid & 31;
    int start = __ldg(&g_off[d]);
    int end = (d == N_NODES - 1) ? ET : __ldg(&g_off[d + 1]);

    float acc0 = 0.f, acc1 = 0.f, denl = 0.f;
    int base = start;
    for (; base + 32 <= end; base += 32) {          // full-chunk fast path
        int2 se = g_epack[base + lane];
        float ex = __int_as_float(se.y);
        denl += ex;
#pragma unroll 8
        for (int j = 0; j < 32; j++) {
            int sj   = __shfl_sync(0xffffffffu, se.x, j);
            float xj = __shfl_sync(0xffffffffu, ex, j);
            __half2 h = *(const __half2*)&g_xlh[(size_t)sj * CO + lane * 2];
            float2 f = __half22float2(h);
            acc0 = fmaf(xj, f.x, acc0);
            acc1 = fmaf(xj, f.y, acc1);
        }
    }
    if (base < end) {
        int p = base + lane;
        int2 se = (p < end) ? g_epack[p] : make_int2(0, 0);
        float ex = __int_as_float(se.y);   // 0 bits -> 0.0f
        denl += ex;
        int cnt = end - base;
        for (int j = 0; j < cnt; j++) {
            int sj   = __shfl_sync(0xffffffffu, se.x, j);
            float xj = __shfl_sync(0xffffffffu, ex, j);
            __half2 h = *(const __half2*)&g_xlh[(size_t)sj * CO + lane * 2];
            float2 f = __half22float2(h);
            acc0 = fmaf(xj, f.x, acc0);
            acc1 = fmaf(xj, f.y, acc1);
        }
    }
#pragma unroll
    for (int o = 16; o; o >>= 1) denl += __shfl_xor_sync(0xffffffffu, denl, o);
    float rden = __frcp_rn(denl);
    if (lane == 0) g_rden[d] = rden;
    float r0 = acc0 * rden + __ldg(&bias[2 * lane]);
    float r1 = acc1 * rden + __ldg(&bias[2 * lane + 1]);
    *(float2*)&g_agg[(size_t)d * CO + lane * 2] = make_float2(r0, r1);

    atomicAdd(&bs1[2 * lane],     r0);
    atomicAdd(&bs1[2 * lane + 1], r1);
    atomicAdd(&bs2[2 * lane],     r0 * r0);
    atomicAdd(&bs2[2 * lane + 1], r1 * r1);

    __syncthreads();
    if (tid < 64) {
        atomicAdd(&g_bnsum[tid],      bs1[tid]);
        atomicAdd(&g_bnsum[64 + tid], bs2[tid]);
    }
}

// ---------------- K8: attention weights (coalesced) --------------------
__global__ __launch_bounds__(256) void k_att(const int* __restrict__ ei,
                                             float* __restrict__ att) {
    int e = blockIdx.x * 256 + threadIdx.x;
    if (e >= ET) return;
    int d = (e < N_EDGES) ? __ldg(&ei[N_EDGES + e]) : (e - N_EDGES);
    att[e] = g_exorig[e] * g_rden[d];
}

// ---------------- K9: BN apply + leaky-relu -> out ----------------------
__global__ __launch_bounds__(256) void k_out(const float* __restrict__ gamma,
                                             const float* __restrict__ beta,
                                             float* __restrict__ out) {
    int i = blockIdx.x * 256 + threadIdx.x;
    if (i >= N_NODES * CO) return;
    int c = i & 63;
    float inv_n = 1.f / (float)N_NODES;
    float mu  = g_bnsum[c] * inv_n;
    float var = g_bnsum[64 + c] * inv_n - mu * mu;
    float v = g_agg[i];   // already includes bias
    float o = __ldg(&gamma[c]) * (v - mu) * rsqrtf(var + 1e-5f) + __ldg(&beta[c]);
    out[i] = o > 0.f ? o : 0.01f * o;
}

// ---------------- launch (single stream) ----------------
extern "C" void kernel_launch(void* const* d_in, const int* in_sizes, int n_in,
                              void* d_out, int out_size) {
    const float* x     = (const float*)d_in[0];
    const int*   ei    = (const int*)  d_in[1];
    const float* emb   = (const float*)d_in[2];
    const float* lw    = (const float*)d_in[3];
    const float* lb    = (const float*)d_in[4];
    const float* ai    = (const float*)d_in[5];
    const float* aj    = (const float*)d_in[6];
    const float* aei   = (const float*)d_in[7];
    const float* aej   = (const float*)d_in[8];
    const float* bias  = (const float*)d_in[9];
    const float* gamma = (const float*)d_in[10];
    const float* beta  = (const float*)d_in[11];

    float* out = (float*)d_out;                  // [N, 64]
    float* att = out + (size_t)N_NODES * CO;     // [ET, 1, 1]

    k_init   <<<(N_NODES + 255) / 256, 256>>>();
    k_gemm   <<<(N_NODES + 255) / 256, 256>>>(x, lw, lb, emb, ai, aj, aei, aej);
    k_hist   <<<(ET + 255) / 256, 256>>>(ei);
    k_scan   <<<NB_SCAN, 1024>>>();
    k_scatter<<<(ET + 255) / 256, 256>>>(ei);
    k_agg_csr<<<(N_NODES * 32) / 256, 256>>>(bias);
    k_att    <<<(ET + 255) / 256, 256>>>(ei, att);
    k_out    <<<(N_NODES * CO + 255) / 256, 256>>>(gamma, beta, out);
}

// round 15
// speedup vs baseline: 1.0884x; 1.0086x over previous
#include <cuda_runtime.h>
#include <cuda_fp16.h>
#include <cstdint>

#define N_NODES 100000
#define N_EDGES 3200000
#define ET      (N_EDGES + N_NODES)   // 3,300,000 (edges + self loops)
#define CI      128
#define CO      64
#define NB_SCAN ((N_NODES + 1023) / 1024)    // 98
#define NB_OUT  ((N_NODES * CO + 255) / 256) // 25000
#define NB_ATT  ((ET + 255) / 256)           // 12891

// ---------------- device scratch (static, no allocation) ----------------
__device__ __align__(16) __half g_xlh[(size_t)N_NODES * CO];  // 12.8 MB fp16 xl
__device__ float g_si[N_NODES];
__device__ float g_sj[N_NODES];
__device__ float g_rden[N_NODES];
__device__ float g_agg[(size_t)N_NODES * CO];   // normalized + bias
__device__ float g_bnsum[2 * CO];
__device__ int   g_deg[N_NODES];
__device__ int   g_off[N_NODES];
__device__ int   g_cursor[N_NODES];
__device__ int   g_bsum[NB_SCAN];
__device__ int   g_bflag[NB_SCAN];
__device__ int2  g_epack[ET];    // (src, float_bits(ex)) grouped by dst
__device__ float g_exorig[ET];   // ex in ORIGINAL edge order (coalesced)

// ---------------- packed f32x2 helpers ----------------
__device__ __forceinline__ unsigned long long pk2(float lo, float hi) {
    unsigned long long r;
    asm("mov.b64 %0, {%1, %2};" : "=l"(r) : "f"(lo), "f"(hi));
    return r;
}
__device__ __forceinline__ float2 upk2(unsigned long long v) {
    float2 f;
    asm("mov.b64 {%0, %1}, %2;" : "=f"(f.x), "=f"(f.y) : "l"(v));
    return f;
}
#define FMA2(d, a, b) asm("fma.rn.f32x2 %0, %1, %2, %0;" : "+l"(d) : "l"(a), "l"(b))

// ---------------- K0: init ----------------
__global__ __launch_bounds__(256) void k_init() {
    int i = blockIdx.x * 256 + threadIdx.x;
    if (i < N_NODES) g_deg[i] = 0;
    if (i < 2 * CO) g_bnsum[i] = 0.f;
    if (i < NB_SCAN) g_bflag[i] = 0;
}

// ---------------- K1: GEMM xl = x @ W^T + b, fused scores --------------
// 256 thr/block, 256 rows/block; thread = 4 rows x 16 cols; f32x2 FMA.
__global__ __launch_bounds__(256) void k_gemm(
    const float* __restrict__ x,  const float* __restrict__ w,
    const float* __restrict__ lb, const float* __restrict__ emb,
    const float* __restrict__ ai, const float* __restrict__ aj,
    const float* __restrict__ aei, const float* __restrict__ aej)
{
    __shared__ float wsT[128 * 68];   // [k][c], row padded to 68 floats
    int tid = threadIdx.x;
    for (int i = tid; i < CO * CI; i += 256) {
        int c = i >> 7, k = i & 127;  // w is [CO][CI] row-major
        wsT[k * 68 + c] = w[i];
    }
    __syncthreads();

    int rbase = blockIdx.x * 256;
    int rl = tid >> 2;                 // 0..63
    int g = (tid & 3) * 16;            // 16-col group
    int m[4]; bool v[4]; int mc[4];
#pragma unroll
    for (int r = 0; r < 4; r++) {
        m[r] = rbase + rl + r * 64;
        v[r] = (m[r] < N_NODES);
        mc[r] = v[r] ? m[r] : (N_NODES - 1);
    }
    const float* xr0 = x + (size_t)mc[0] * CI;
    const float* xr1 = x + (size_t)mc[1] * CI;
    const float* xr2 = x + (size_t)mc[2] * CI;
    const float* xr3 = x + (size_t)mc[3] * CI;

    unsigned long long acc[4][8];      // 4 rows x 8 f32x2 = 16 cols
#pragma unroll
    for (int r = 0; r < 4; r++)
#pragma unroll
        for (int t = 0; t < 8; t++) acc[r][t] = 0ull;

    for (int k0 = 0; k0 < 128; k0 += 4) {
        float4 xv0 = *(const float4*)(xr0 + k0);
        float4 xv1 = *(const float4*)(xr1 + k0);
        float4 xv2 = *(const float4*)(xr2 + k0);
        float4 xv3 = *(const float4*)(xr3 + k0);
#pragma unroll
        for (int q = 0; q < 4; q++) {
            unsigned long long xs0 = pk2((&xv0.x)[q], (&xv0.x)[q]);
            unsigned long long xs1 = pk2((&xv1.x)[q], (&xv1.x)[q]);
            unsigned long long xs2 = pk2((&xv2.x)[q], (&xv2.x)[q]);
            unsigned long long xs3 = pk2((&xv3.x)[q], (&xv3.x)[q]);
            const ulonglong2* wp = (const ulonglong2*)&wsT[(k0 + q) * 68 + g];
#pragma unroll
            for (int j = 0; j < 4; j++) {
                ulonglong2 wv = wp[j];               // LDS.128 = 2 packed pairs
                FMA2(acc[0][2*j],   xs0, wv.x); FMA2(acc[0][2*j+1], xs0, wv.y);
                FMA2(acc[1][2*j],   xs1, wv.x); FMA2(acc[1][2*j+1], xs1, wv.y);
                FMA2(acc[2][2*j],   xs2, wv.x); FMA2(acc[2][2*j+1], xs2, wv.y);
                FMA2(acc[3][2*j],   xs3, wv.x); FMA2(acc[3][2*j+1], xs3, wv.y);
            }
        }
    }

    // epilogue per row: bias, scores, fp16 xl store; reduce over 4 lanes
#pragma unroll
    for (int r = 0; r < 4; r++) {
        float p_i = 0.f, p_j = 0.f;
        unsigned hu[8];
#pragma unroll
        for (int t = 0; t < 8; t++) {
            float2 f = upk2(acc[r][t]);
            float o0 = f.x + __ldg(&lb[g + 2*t]);
            float o1 = f.y + __ldg(&lb[g + 2*t + 1]);
            p_i = fmaf(o0, __ldg(&ai[g + 2*t]),     p_i);
            p_i = fmaf(o1, __ldg(&ai[g + 2*t + 1]), p_i);
            p_j = fmaf(o0, __ldg(&aj[g + 2*t]),     p_j);
            p_j = fmaf(o1, __ldg(&aj[g + 2*t + 1]), p_j);
            __half2 hh = __floats2half2_rn(o0, o1);
            hu[t] = *reinterpret_cast<unsigned*>(&hh);
        }
        if (v[r]) {
            uint4* dstp = (uint4*)&g_xlh[(size_t)m[r] * CO + g];
            dstp[0] = make_uint4(hu[0], hu[1], hu[2], hu[3]);
            dstp[1] = make_uint4(hu[4], hu[5], hu[6], hu[7]);
        }
        const float* er = emb + (size_t)mc[r] * CO + g;
#pragma unroll
        for (int c = 0; c < 16; c += 4) {
            float4 ev = *(const float4*)(er + c);
#pragma unroll
            for (int q = 0; q < 4; q++) {
                p_i = fmaf((&ev.x)[q], __ldg(&aei[g + c + q]), p_i);
                p_j = fmaf((&ev.x)[q], __ldg(&aej[g + c + q]), p_j);
            }
        }
        p_i += __shfl_xor_sync(0xffffffffu, p_i, 1);
        p_j += __shfl_xor_sync(0xffffffffu, p_j, 1);
        p_i += __shfl_xor_sync(0xffffffffu, p_i, 2);
        p_j += __shfl_xor_sync(0xffffffffu, p_j, 2);
        if (v[r] && (tid & 3) == 0) { g_si[m[r]] = p_i; g_sj[m[r]] = p_j; }
    }
}

// ---------------- CSR build: histogram + single-pass scan ---------------
__global__ __launch_bounds__(256) void k_hist(const int* __restrict__ ei) {
    int e = blockIdx.x * 256 + threadIdx.x;
    if (e >= ET) return;
    int d = (e < N_EDGES) ? __ldg(&ei[N_EDGES + e]) : (e - N_EDGES);
    atomicAdd(&g_deg[d], 1);
}

// One-pass chained scan: 98 blocks (< 148 SMs -> all resident wave 1).
__global__ __launch_bounds__(1024) void k_scan() {
    __shared__ int sh[2][1024];
    __shared__ int bpre_sh;
    int b = blockIdx.x;
    int t = threadIdx.x;
    int i = b * 1024 + t;
    int v = (i < N_NODES) ? g_deg[i] : 0;
    sh[0][t] = v;
    __syncthreads();
    int cur = 0;
#pragma unroll
    for (int ofs = 1; ofs < 1024; ofs <<= 1) {
        int nxt = cur ^ 1;
        int val = sh[cur][t];
        if (t >= ofs) val += sh[cur][t - ofs];
        sh[nxt][t] = val;
        __syncthreads();
        cur = nxt;
    }
    if (t == 0) {
        g_bsum[b] = sh[cur][1023];
        __threadfence();
        atomicExch(&g_bflag[b], 1);
    }
    if (t < 32) {
        int acc = 0;
        for (int p = t; p < b; p += 32) {
            while (atomicAdd(&g_bflag[p], 0) == 0) { }
            acc += atomicAdd(&g_bsum[p], 0);
        }
#pragma unroll
        for (int o = 16; o; o >>= 1) acc += __shfl_xor_sync(0xffffffffu, acc, o);
        if (t == 0) bpre_sh = acc;
    }
    __syncthreads();
    if (i < N_NODES) {
        int excl = sh[cur][t] - v + bpre_sh;
        g_off[i] = excl;
        g_cursor[i] = excl;
    }
}

// scatter: compute ex once; random epack store + coalesced exorig store
__global__ __launch_bounds__(256) void k_scatter(const int* __restrict__ ei) {
    int e = blockIdx.x * 256 + threadIdx.x;
    if (e >= ET) return;
    int s, d;
    if (e < N_EDGES) { s = __ldg(&ei[e]); d = __ldg(&ei[N_EDGES + e]); }
    else             { s = e - N_EDGES; d = s; }
    float a = g_si[d] + g_sj[s];
    a = a > 0.f ? a : 0.2f * a;
    float ex = __expf(a);
    g_exorig[e] = ex;                        // coalesced
    int pos = atomicAdd(&g_cursor[d], 1);
    g_epack[pos] = make_int2(s, __float_as_int(ex));
}

// ---------------- K7: CSR aggregate + fused BN stats --------------------
// One warp per dst node; grid is EXACTLY 12500 blocks (100000 warps).
// NO metadata prefetch (measured +12-18us regression with it).
__global__ __launch_bounds__(256) void k_agg_csr(const float* __restrict__ bias) {
    __shared__ float bs1[64], bs2[64];
    int tid = threadIdx.x;
    if (tid < 64) { bs1[tid] = 0.f; bs2[tid] = 0.f; }
    __syncthreads();

    int d = (blockIdx.x * 256 + tid) >> 5;
    int lane = tid & 31;
    int start = __ldg(&g_off[d]);
    int end = (d == N_NODES - 1) ? ET : __ldg(&g_off[d + 1]);

    float acc0 = 0.f, acc1 = 0.f, denl = 0.f;
    int base = start;
    for (; base + 32 <= end; base += 32) {          // full-chunk fast path
        int2 se = g_epack[base + lane];
        float ex = __int_as_float(se.y);
        denl += ex;
#pragma unroll 8
        for (int j = 0; j < 32; j++) {
            int sj   = __shfl_sync(0xffffffffu, se.x, j);
            float xj = __shfl_sync(0xffffffffu, ex, j);
            __half2 h = *(const __half2*)&g_xlh[(size_t)sj * CO + lane * 2];
            float2 f = __half22float2(h);
            acc0 = fmaf(xj, f.x, acc0);
            acc1 = fmaf(xj, f.y, acc1);
        }
    }
    if (base < end) {
        int p = base + lane;
        int2 se = (p < end) ? g_epack[p] : make_int2(0, 0);
        float ex = __int_as_float(se.y);   // 0 bits -> 0.0f
        denl += ex;
        int cnt = end - base;
        for (int j = 0; j < cnt; j++) {
            int sj   = __shfl_sync(0xffffffffu, se.x, j);
            float xj = __shfl_sync(0xffffffffu, ex, j);
            __half2 h = *(const __half2*)&g_xlh[(size_t)sj * CO + lane * 2];
            float2 f = __half22float2(h);
            acc0 = fmaf(xj, f.x, acc0);
            acc1 = fmaf(xj, f.y, acc1);
        }
    }
#pragma unroll
    for (int o = 16; o; o >>= 1) denl += __shfl_xor_sync(0xffffffffu, denl, o);
    float rden = __frcp_rn(denl);
    if (lane == 0) g_rden[d] = rden;
    float r0 = acc0 * rden + __ldg(&bias[2 * lane]);
    float r1 = acc1 * rden + __ldg(&bias[2 * lane + 1]);
    *(float2*)&g_agg[(size_t)d * CO + lane * 2] = make_float2(r0, r1);

    atomicAdd(&bs1[2 * lane],     r0);
    atomicAdd(&bs1[2 * lane + 1], r1);
    atomicAdd(&bs2[2 * lane],     r0 * r0);
    atomicAdd(&bs2[2 * lane + 1], r1 * r1);

    __syncthreads();
    if (tid < 64) {
        atomicAdd(&g_bnsum[tid],      bs1[tid]);
        atomicAdd(&g_bnsum[64 + tid], bs2[tid]);
    }
}

// ---------------- K8: merged tail — BN apply+lrelu AND att weights -----
// Blocks [0, NB_OUT): out elements. Blocks [NB_OUT, NB_OUT+NB_ATT): att.
__global__ __launch_bounds__(256) void k_tail(const int* __restrict__ ei,
                                              const float* __restrict__ gamma,
                                              const float* __restrict__ beta,
                                              float* __restrict__ out,
                                              float* __restrict__ att) {
    int b = blockIdx.x;
    if (b < NB_OUT) {
        int i = b * 256 + threadIdx.x;
        if (i >= N_NODES * CO) return;
        int c = i & 63;
        float inv_n = 1.f / (float)N_NODES;
        float mu  = g_bnsum[c] * inv_n;
        float var = g_bnsum[64 + c] * inv_n - mu * mu;
        float v = g_agg[i];   // already includes bias
        float o = __ldg(&gamma[c]) * (v - mu) * rsqrtf(var + 1e-5f) + __ldg(&beta[c]);
        out[i] = o > 0.f ? o : 0.01f * o;
    } else {
        int e = (b - NB_OUT) * 256 + threadIdx.x;
        if (e >= ET) return;
        int d = (e < N_EDGES) ? __ldg(&ei[N_EDGES + e]) : (e - N_EDGES);
        att[e] = g_exorig[e] * g_rden[d];
    }
}

// ---------------- launch (single stream) ----------------
extern "C" void kernel_launch(void* const* d_in, const int* in_sizes, int n_in,
                              void* d_out, int out_size) {
    const float* x     = (const float*)d_in[0];
    const int*   ei    = (const int*)  d_in[1];
    const float* emb   = (const float*)d_in[2];
    const float* lw    = (const float*)d_in[3];
    const float* lb    = (const float*)d_in[4];
    const float* ai    = (const float*)d_in[5];
    const float* aj    = (const float*)d_in[6];
    const float* aei   = (const float*)d_in[7];
    const float* aej   = (const float*)d_in[8];
    const float* bias  = (const float*)d_in[9];
    const float* gamma = (const float*)d_in[10];
    const float* beta  = (const float*)d_in[11];

    float* out = (float*)d_out;                  // [N, 64]
    float* att = out + (size_t)N_NODES * CO;     // [ET, 1, 1]

    k_init   <<<(N_NODES + 255) / 256, 256>>>();
    k_gemm   <<<(N_NODES + 255) / 256, 256>>>(x, lw, lb, emb, ai, aj, aei, aej);
    k_hist   <<<(ET + 255) / 256, 256>>>(ei);
    k_scan   <<<NB_SCAN, 1024>>>();
    k_scatter<<<(ET + 255) / 256, 256>>>(ei);
    k_agg_csr<<<(N_NODES * 32) / 256, 256>>>(bias);
    k_tail   <<<NB_OUT + NB_ATT, 256>>>(ei, gamma, beta, out, att);
}